// round 15
// baseline (speedup 1.0000x reference)
#include <cuda_runtime.h>
#include <cuda_fp16.h>
#include <cstdint>
#include <math.h>

// Problem constants
#define TOKENS 8192      // B*S = 4*2048
#define DM     1024
#define DI     4096
#define SEQ    2048
#define BATCH  4
#define NH     16
#define HD     64
#define RMS_EPS 1.1920929e-07f
#define LOG2E  1.44269504088896f

// ---------------- scratch (no allocations allowed) ----------------
__device__ __half g_x16 [TOKENS * DM];
__device__ __half g_q16 [TOKENS * DM];
__device__ __half g_k16 [TOKENS * DM];
__device__ __half g_v16 [TOKENS * DM];
__device__ __half g_c16 [TOKENS * DM];   // ctx fp16
__device__ __half g_y16 [TOKENS * DM];   // y = x + attn_out (fp16 operand copy)
__device__ float  g_yf  [TOKENS * DM];   // y fp32 (exact residual branch)
__device__ __half g_f16 [TOKENS * DI];   // ff1 fp16
__device__ __half g_t16 [TOKENS * DM];   // ff2 fp16
__device__ float  g_r   [TOKENS];        // per-row rms scale
// transposed fp16 weights [N][K]
__device__ __half g_wqt[DM * DM];
__device__ __half g_wkt[DM * DM];
__device__ __half g_wvt[DM * DM];
__device__ __half g_wot[DM * DM];
__device__ __half g_w1t[DI * DM];
__device__ __half g_w2t[DM * DI];

// ================= helpers =================
__device__ __forceinline__ uint32_t smem_u32(const void* p) {
    return (uint32_t)__cvta_generic_to_shared(p);
}
__device__ __forceinline__ void cp16(uint32_t s, const void* g) {
    asm volatile("cp.async.cg.shared.global [%0], [%1], 16;\n"
                 :: "r"(s), "l"(__cvta_generic_to_global(g)) : "memory");
}
__device__ __forceinline__ void cp_commit() {
    asm volatile("cp.async.commit_group;\n" ::: "memory");
}
template<int N>
__device__ __forceinline__ void cp_wait() {
    asm volatile("cp.async.wait_group %0;\n" :: "n"(N) : "memory");
}
__device__ __forceinline__ void mma_f16_16n8k16(float* c, const uint32_t* a,
                                                uint32_t b0, uint32_t b1) {
    asm volatile(
        "mma.sync.aligned.m16n8k16.row.col.f32.f16.f16.f32 "
        "{%0,%1,%2,%3}, {%4,%5,%6,%7}, {%8,%9}, {%0,%1,%2,%3};"
        : "+f"(c[0]), "+f"(c[1]), "+f"(c[2]), "+f"(c[3])
        : "r"(a[0]), "r"(a[1]), "r"(a[2]), "r"(a[3]), "r"(b0), "r"(b1));
}
__device__ __forceinline__ void ldsm_x4(uint32_t& r0, uint32_t& r1, uint32_t& r2,
                                        uint32_t& r3, uint32_t addr) {
    asm volatile("ldmatrix.sync.aligned.m8n8.x4.shared.b16 {%0,%1,%2,%3}, [%4];"
                 : "=r"(r0), "=r"(r1), "=r"(r2), "=r"(r3) : "r"(addr));
}
__device__ __forceinline__ void ldsm_x4_t(uint32_t& r0, uint32_t& r1, uint32_t& r2,
                                          uint32_t& r3, uint32_t addr) {
    asm volatile("ldmatrix.sync.aligned.m8n8.x4.trans.shared.b16 {%0,%1,%2,%3}, [%4];"
                 : "=r"(r0), "=r"(r1), "=r"(r2), "=r"(r3) : "r"(addr));
}
__device__ __forceinline__ float ex2(float x) {
    float y;
    asm("ex2.approx.f32 %0, %1;" : "=f"(y) : "f"(x));
    return y;
}
__device__ __forceinline__ uint32_t ldh32(const __half* p) {
    return *(const uint32_t*)p;
}
__device__ __forceinline__ uint32_t packh2(float a, float b) {
    __half2 h = __floats2half2_rn(a, b);
    return *(uint32_t*)&h;
}

// ================= pre-pass: weight transpose fp32[R][C] -> fp16[C][R] =================
__global__ __launch_bounds__(256)
void trans_cvt_kernel(const float* Wq, const float* Wk, const float* Wv,
                      const float* Wo, const float* W1, const float* W2,
                      __half* oq, __half* ok, __half* ov,
                      __half* oo, __half* o1, __half* o2)
{
    const float* in; __half* out; int R, C; float scale = 1.f;
    switch (blockIdx.z) {
        case 0: in = Wq; out = oq; R = DM; C = DM; scale = 0.125f * LOG2E; break;
        case 1: in = Wk; out = ok; R = DM; C = DM; break;
        case 2: in = Wv; out = ov; R = DM; C = DM; break;
        case 3: in = Wo; out = oo; R = DM; C = DM; break;
        case 4: in = W1; out = o1; R = DM; C = DI; break;
        default: in = W2; out = o2; R = DI; C = DM; break;
    }
    int c0 = blockIdx.x * 32, r0 = blockIdx.y * 32;
    if (c0 >= C || r0 >= R) return;
    __shared__ float t[32][33];
    int x = threadIdx.x & 31, y = (threadIdx.x >> 5) * 4;
    #pragma unroll
    for (int dy = 0; dy < 4; dy++)
        t[y + dy][x] = in[(size_t)(r0 + y + dy) * C + c0 + x];
    __syncthreads();
    #pragma unroll
    for (int dy = 0; dy < 4; dy++)
        out[(size_t)(c0 + y + dy) * R + r0 + x] = __float2half_rn(t[x][y + dy] * scale);
}

__global__ __launch_bounds__(256)
void cvt16_kernel(const float4* __restrict__ in, __half2* __restrict__ out, int n4)
{
    int i = blockIdx.x * 256 + threadIdx.x;
    if (i < n4) {
        float4 v = in[i];
        out[2 * i]     = __floats2half2_rn(v.x, v.y);
        out[2 * i + 1] = __floats2half2_rn(v.z, v.w);
    }
}

// ================= fp16 mma.sync GEMM (BK=64, warp 64x64, single-sync loop) =================
// Modes: fused epilogues.
#define M_QKV 0   // C = fp16(acc)
#define M_WO  1   // y16 = fp16(x + acc), yf = x + acc (fp32)
#define M_W1  2   // C = fp16(relu(acc) * r[row])
#define M_W2  3   // C = fp16(acc)
#define HSTR 72
#define H_TILE (128 * HSTR)
#define GEMM_DSM ((4 * H_TILE) * 2)                // 73728 B

template<int MODE>
__global__ __launch_bounds__(128, 2)
void gemm_h(const __half* __restrict__ A,
            const __half* __restrict__ B0, const __half* __restrict__ B1,
            const __half* __restrict__ B2,
            __half* __restrict__ C0, __half* __restrict__ C1, __half* __restrict__ C2,
            const float* __restrict__ xf,   // M_WO: residual input
            float* __restrict__ yf,         // M_WO: fp32 y output
            const float* __restrict__ rvec, // M_W1: per-row scale
            int M, int N, int K)
{
    extern __shared__ __half hs[];
    __half* As = hs;
    __half* Bs = hs + 2 * H_TILE;

    const __half* B = (blockIdx.z == 0) ? B0 : (blockIdx.z == 1 ? B1 : B2);
    __half*       C = (blockIdx.z == 0) ? C0 : (blockIdx.z == 1 ? C1 : C2);

    const int tid  = threadIdx.x;
    const int lane = tid & 31;
    const int warp = tid >> 5;
    const int warpM = warp & 1;
    const int warpN = warp >> 1;
    const int grp = lane >> 2;
    const int qd  = lane & 3;
    const int li  = lane & 7;
    const int sel = lane >> 3;
    const int rowBase = blockIdx.y * 128;
    const int colBase = blockIdx.x * 128;
    const int numK = K >> 6;

    const uint32_t sAu = smem_u32(As);
    const uint32_t sBu = smem_u32(Bs);

    const int aOff = (warpM * 64 + (sel & 1) * 8 + li) * HSTR + (sel >> 1) * 8;
    const int bOff = (warpN * 64 + (sel >> 1) * 8 + li) * HSTR + (sel & 1) * 8;

    float acc[4][8][4];
    #pragma unroll
    for (int i = 0; i < 4; i++)
        #pragma unroll
        for (int j = 0; j < 8; j++)
            #pragma unroll
            for (int e = 0; e < 4; e++) acc[i][j][e] = 0.f;

    auto load_stage = [&](int chunk, int stage) {
        const int k0 = chunk << 6;
        const uint32_t dA = sAu + stage * H_TILE * 2;
        const uint32_t dB = sBu + stage * H_TILE * 2;
        #pragma unroll
        for (int it = 0; it < 8; it++) {
            int i = tid + it * 128;
            int r = i >> 3, c8 = i & 7;
            cp16(dA + (r * HSTR + c8 * 8) * 2,
                 A + (size_t)(rowBase + r) * K + k0 + c8 * 8);
        }
        #pragma unroll
        for (int it = 0; it < 8; it++) {
            int i = tid + it * 128;
            int r = i >> 3, c8 = i & 7;
            cp16(dB + (r * HSTR + c8 * 8) * 2,
                 B + (size_t)(colBase + r) * K + k0 + c8 * 8);
        }
    };

    load_stage(0, 0);
    cp_commit();

    // single-sync pipeline: [wait data | sync (frees other buffer) | issue next | compute]
    for (int i = 0; i < numK; i++) {
        cp_wait<0>();
        __syncthreads();
        if (i + 1 < numK) load_stage(i + 1, (i + 1) & 1);
        cp_commit();

        const uint32_t pAu = sAu + (i & 1) * H_TILE * 2 + aOff * 2;
        const uint32_t pBu = sBu + (i & 1) * H_TILE * 2 + bOff * 2;

        #pragma unroll
        for (int ks = 0; ks < 4; ks++) {
            const int k0 = ks * 16;
            uint32_t afr[4][4], bfr[4][4];
            #pragma unroll
            for (int mt = 0; mt < 4; mt++)
                ldsm_x4(afr[mt][0], afr[mt][1], afr[mt][2], afr[mt][3],
                        pAu + (mt * 16 * HSTR + k0) * 2);
            #pragma unroll
            for (int np = 0; np < 4; np++)
                ldsm_x4(bfr[np][0], bfr[np][1], bfr[np][2], bfr[np][3],
                        pBu + (np * 16 * HSTR + k0) * 2);
            #pragma unroll
            for (int mt = 0; mt < 4; mt++) {
                #pragma unroll
                for (int np = 0; np < 4; np++) {
                    mma_f16_16n8k16(acc[mt][2 * np    ], afr[mt], bfr[np][0], bfr[np][1]);
                    mma_f16_16n8k16(acc[mt][2 * np + 1], afr[mt], bfr[np][2], bfr[np][3]);
                }
            }
        }
    }

    // epilogue (per mode)
    #pragma unroll
    for (int mt = 0; mt < 4; mt++) {
        int r0 = rowBase + warpM * 64 + mt * 16 + grp;
        float rs0 = 1.f, rs1 = 1.f;
        if (MODE == M_W1) { rs0 = rvec[r0]; rs1 = rvec[r0 + 8]; }
        #pragma unroll
        for (int nt = 0; nt < 8; nt++) {
            int c0 = colBase + warpN * 64 + nt * 8 + qd * 2;
            float v[4] = {acc[mt][nt][0], acc[mt][nt][1], acc[mt][nt][2], acc[mt][nt][3]};
            if (MODE == M_W1) {
                v[0] = fmaxf(v[0], 0.f) * rs0; v[1] = fmaxf(v[1], 0.f) * rs0;
                v[2] = fmaxf(v[2], 0.f) * rs1; v[3] = fmaxf(v[3], 0.f) * rs1;
            }
            if (MODE == M_WO) {
                float2 x0 = *(const float2*)&xf[(size_t)(r0    ) * N + c0];
                float2 x8 = *(const float2*)&xf[(size_t)(r0 + 8) * N + c0];
                v[0] += x0.x; v[1] += x0.y; v[2] += x8.x; v[3] += x8.y;
                *(float2*)&yf[(size_t)(r0    ) * N + c0] = make_float2(v[0], v[1]);
                *(float2*)&yf[(size_t)(r0 + 8) * N + c0] = make_float2(v[2], v[3]);
            }
            *(__half2*)&C[(size_t)(r0    ) * N + c0] = __floats2half2_rn(v[0], v[1]);
            *(__half2*)&C[(size_t)(r0 + 8) * N + c0] = __floats2half2_rn(v[2], v[3]);
        }
    }
}

// ================= fp16 flash attention (no-max softmax, register P) =================
#define AKST 72
#define ATT_K_TILE (64 * AKST)
#define ATT_VS_OFF (2 * ATT_K_TILE)
#define ATT_DSM ((4 * ATT_K_TILE) * 2)    // 36864 B
#define NKT (SEQ / 64)

__global__ __launch_bounds__(256, 2)
void attn_h_kernel(const __half* __restrict__ Q, const __half* __restrict__ K,
                   const __half* __restrict__ V, __half* __restrict__ O)
{
    extern __shared__ __half smh[];
    __half* Ks = smh;
    __half* Vs = smh + ATT_VS_OFF;

    const int b  = blockIdx.z;
    const int hh = blockIdx.y;
    const int qt = blockIdx.x;
    const int tid = threadIdx.x;
    const int lane = tid & 31;
    const int w = tid >> 5;
    const int grp = lane >> 2;
    const int qd  = lane & 3;
    const int li  = lane & 7;
    const int sel = lane >> 3;

    const size_t base = ((size_t)b * SEQ) * DM + (size_t)hh * HD;
    const __half* Kg = K + base;
    const __half* Vg = V + base;

    uint32_t qa[4][4];
    {
        const __half* q0 = Q + base + (size_t)(qt * 128 + w * 16 + grp) * DM;
        const __half* q8 = q0 + 8 * (size_t)DM;
        #pragma unroll
        for (int ks = 0; ks < 4; ks++) {
            qa[ks][0] = ldh32(&q0[ks * 16 + 2 * qd    ]);
            qa[ks][1] = ldh32(&q8[ks * 16 + 2 * qd    ]);
            qa[ks][2] = ldh32(&q0[ks * 16 + 2 * qd + 8]);
            qa[ks][3] = ldh32(&q8[ks * 16 + 2 * qd + 8]);
        }
    }

    float o[8][4];
    #pragma unroll
    for (int i = 0; i < 8; i++)
        #pragma unroll
        for (int e = 0; e < 4; e++) o[i][e] = 0.f;
    float l0p = 0.f, l1p = 0.f;

    const uint32_t ksU = smem_u32(Ks);
    const uint32_t vsU = smem_u32(Vs);
    const int kOff = ((sel >> 1) * 8 + li) * AKST + (sel & 1) * 8;
    const int vOff = ((sel & 1) * 8 + li) * AKST + (sel >> 1) * 8;

    auto load_tile = [&](int t, int buf) {
        const __half* Kn = Kg + (size_t)t * 64 * DM;
        const __half* Vn = Vg + (size_t)t * 64 * DM;
        uint32_t kb = ksU + buf * ATT_K_TILE * 2;
        uint32_t vb = vsU + buf * ATT_K_TILE * 2;
        #pragma unroll
        for (int it = 0; it < 2; it++) {
            int i = tid + it * 256;
            int r = i >> 3, c8 = i & 7;
            cp16(kb + (r * AKST + c8 * 8) * 2, Kn + (size_t)r * DM + c8 * 8);
        }
        #pragma unroll
        for (int it = 0; it < 2; it++) {
            int i = tid + it * 256;
            int r = i >> 3, c8 = i & 7;
            cp16(vb + (r * AKST + c8 * 8) * 2, Vn + (size_t)r * DM + c8 * 8);
        }
    };

    load_tile(0, 0);
    cp_commit();

    for (int kt = 0; kt < NKT; kt++) {
        cp_wait<0>();
        __syncthreads();

        if (kt + 1 < NKT) {
            load_tile(kt + 1, (kt + 1) & 1);
            cp_commit();
        }

        const uint32_t kbU = ksU + (kt & 1) * ATT_K_TILE * 2 + kOff * 2;
        const uint32_t vbU = vsU + (kt & 1) * ATT_K_TILE * 2 + vOff * 2;

        float s[8][4];
        #pragma unroll
        for (int nt = 0; nt < 8; nt++)
            #pragma unroll
            for (int e = 0; e < 4; e++) s[nt][e] = 0.f;

        #pragma unroll
        for (int ks = 0; ks < 4; ks++) {
            #pragma unroll
            for (int ntp = 0; ntp < 4; ntp++) {
                uint32_t b0, b1, b2, b3;
                ldsm_x4(b0, b1, b2, b3, kbU + (ntp * 16 * AKST + ks * 16) * 2);
                mma_f16_16n8k16(s[2 * ntp    ], qa[ks], b0, b1);
                mma_f16_16n8k16(s[2 * ntp + 1], qa[ks], b2, b3);
            }
        }

        uint32_t pa0[8], pa1[8];
        #pragma unroll
        for (int nt = 0; nt < 8; nt++) {
            float e00 = ex2(s[nt][0]), e01 = ex2(s[nt][1]);
            float e10 = ex2(s[nt][2]), e11 = ex2(s[nt][3]);
            l0p += e00 + e01;
            l1p += e10 + e11;
            pa0[nt] = packh2(e00, e01);
            pa1[nt] = packh2(e10, e11);
        }

        #pragma unroll
        for (int ks2 = 0; ks2 < 4; ks2++) {
            uint32_t pa[4] = {pa0[2 * ks2], pa1[2 * ks2], pa0[2 * ks2 + 1], pa1[2 * ks2 + 1]};
            #pragma unroll
            for (int dp = 0; dp < 4; dp++) {
                uint32_t b0, b1, b2, b3;
                ldsm_x4_t(b0, b1, b2, b3, vbU + (ks2 * 16 * AKST + dp * 16) * 2);
                mma_f16_16n8k16(o[2 * dp    ], pa, b0, b1);
                mma_f16_16n8k16(o[2 * dp + 1], pa, b2, b3);
            }
        }
    }

    l0p += __shfl_xor_sync(0xffffffffu, l0p, 1);
    l0p += __shfl_xor_sync(0xffffffffu, l0p, 2);
    l1p += __shfl_xor_sync(0xffffffffu, l1p, 1);
    l1p += __shfl_xor_sync(0xffffffffu, l1p, 2);
    float i0 = 1.f / l0p, i1 = 1.f / l1p;
    __half* o0 = O + base + (size_t)(qt * 128 + w * 16 + grp) * DM;
    __half* o8 = o0 + 8 * (size_t)DM;
    #pragma unroll
    for (int nt2 = 0; nt2 < 8; nt2++) {
        *(__half2*)&o0[nt2 * 8 + 2 * qd] = __floats2half2_rn(o[nt2][0] * i0, o[nt2][1] * i0);
        *(__half2*)&o8[nt2 * 8 + 2 * qd] = __floats2half2_rn(o[nt2][2] * i1, o[nt2][3] * i1);
    }
}

// ---------------- per-row rms scale from y16 ----------------
__global__ __launch_bounds__(256)
void stats_kernel(const __half* __restrict__ y16, float* __restrict__ rvec)
{
    __shared__ float red[8];
    const int row = blockIdx.x;
    const int t = threadIdx.x;
    const uint2 u = ((const uint2*)(y16 + (size_t)row * DM))[t];   // 4 halves
    float2 a = __half22float2(*(const __half2*)&u.x);
    float2 b = __half22float2(*(const __half2*)&u.y);
    float ss = a.x * a.x + a.y * a.y + b.x * b.x + b.y * b.y;
    #pragma unroll
    for (int off = 16; off >= 1; off >>= 1)
        ss += __shfl_xor_sync(0xffffffffu, ss, off);
    if ((t & 31) == 0) red[t >> 5] = ss;
    __syncthreads();
    if (t == 0) {
        float tot = 0.f;
        #pragma unroll
        for (int w = 0; w < 8; w++) tot += red[w];
        rvec[row] = rsqrtf(tot * (1.0f / DM) + RMS_EPS);
    }
}

// ---------------- final: out = rmsnorm(y*r + t16) ----------------
__global__ __launch_bounds__(256)
void final_kernel(const float* __restrict__ yf, const float* __restrict__ rvec,
                  const __half* __restrict__ t16, float* __restrict__ Out)
{
    __shared__ float red[8];
    const int row = blockIdx.x;
    const int t = threadIdx.x;
    const float rv = rvec[row];

    float4 y = ((const float4*)(yf + (size_t)row * DM))[t];
    const uint2 u = ((const uint2*)(t16 + (size_t)row * DM))[t];
    float2 ta = __half22float2(*(const __half2*)&u.x);
    float2 tb = __half22float2(*(const __half2*)&u.y);
    float4 s = make_float4(y.x * rv + ta.x, y.y * rv + ta.y,
                           y.z * rv + tb.x, y.w * rv + tb.y);
    float ss = s.x * s.x + s.y * s.y + s.z * s.z + s.w * s.w;

    #pragma unroll
    for (int off = 16; off >= 1; off >>= 1)
        ss += __shfl_xor_sync(0xffffffffu, ss, off);
    if ((t & 31) == 0) red[t >> 5] = ss;
    __syncthreads();

    float tot = 0.f;
    #pragma unroll
    for (int w = 0; w < 8; w++) tot += red[w];

    float inv = rsqrtf(tot * (1.0f / DM) + RMS_EPS);
    ((float4*)(Out + (size_t)row * DM))[t] =
        make_float4(s.x * inv, s.y * inv, s.z * inv, s.w * inv);
}

// ---------------- launch ----------------
extern "C" void kernel_launch(void* const* d_in, const int* in_sizes, int n_in,
                              void* d_out, int out_size)
{
    const float* x  = (const float*)d_in[0];
    const float* Wq = (const float*)d_in[1];
    const float* Wk = (const float*)d_in[2];
    const float* Wv = (const float*)d_in[3];
    const float* Wo = (const float*)d_in[4];
    const float* W1 = (const float*)d_in[5];
    const float* W2 = (const float*)d_in[6];
    float* out = (float*)d_out;

    __half *x16, *q16, *k16, *v16, *c16, *y16, *f16, *t16;
    __half *wqt, *wkt, *wvt, *wot, *w1t, *w2t;
    float *yfp, *rvec;
    cudaGetSymbolAddress((void**)&x16, g_x16);
    cudaGetSymbolAddress((void**)&q16, g_q16);
    cudaGetSymbolAddress((void**)&k16, g_k16);
    cudaGetSymbolAddress((void**)&v16, g_v16);
    cudaGetSymbolAddress((void**)&c16, g_c16);
    cudaGetSymbolAddress((void**)&y16, g_y16);
    cudaGetSymbolAddress((void**)&f16, g_f16);
    cudaGetSymbolAddress((void**)&t16, g_t16);
    cudaGetSymbolAddress((void**)&yfp, g_yf);
    cudaGetSymbolAddress((void**)&rvec, g_r);
    cudaGetSymbolAddress((void**)&wqt, g_wqt);
    cudaGetSymbolAddress((void**)&wkt, g_wkt);
    cudaGetSymbolAddress((void**)&wvt, g_wvt);
    cudaGetSymbolAddress((void**)&wot, g_wot);
    cudaGetSymbolAddress((void**)&w1t, g_w1t);
    cudaGetSymbolAddress((void**)&w2t, g_w2t);

    cudaFuncSetAttribute(attn_h_kernel, cudaFuncAttributeMaxDynamicSharedMemorySize,
                         ATT_DSM);
    cudaFuncSetAttribute((const void*)gemm_h<M_QKV>,
                         cudaFuncAttributeMaxDynamicSharedMemorySize, GEMM_DSM);
    cudaFuncSetAttribute((const void*)gemm_h<M_WO>,
                         cudaFuncAttributeMaxDynamicSharedMemorySize, GEMM_DSM);
    cudaFuncSetAttribute((const void*)gemm_h<M_W1>,
                         cudaFuncAttributeMaxDynamicSharedMemorySize, GEMM_DSM);
    cudaFuncSetAttribute((const void*)gemm_h<M_W2>,
                         cudaFuncAttributeMaxDynamicSharedMemorySize, GEMM_DSM);

    // ---- pre-pass ----
    trans_cvt_kernel<<<dim3(DI / 32, DI / 32, 6), 256>>>(
        Wq, Wk, Wv, Wo, W1, W2, wqt, wkt, wvt, wot, w1t, w2t);
    cvt16_kernel<<<(TOKENS * DM / 4 + 255) / 256, 256>>>(
        (const float4*)x, (__half2*)x16, TOKENS * DM / 4);

    dim3 g_qkv(DM / 128, TOKENS / 128, 3);
    dim3 g_dm (DM / 128, TOKENS / 128, 1);
    dim3 g_di (DI / 128, TOKENS / 128, 1);

    // QKV fused
    gemm_h<M_QKV><<<g_qkv, 128, GEMM_DSM>>>(
        x16, wqt, wkt, wvt, q16, k16, v16, nullptr, nullptr, nullptr, TOKENS, DM, DM);

    attn_h_kernel<<<dim3(SEQ / 128, NH, BATCH), 256, ATT_DSM>>>(q16, k16, v16, c16);

    // Wo projection + fused residual: y = x + ctx@Wo  (y16 + yf)
    gemm_h<M_WO><<<g_dm, 128, GEMM_DSM>>>(
        c16, wot, wot, wot, y16, y16, y16, x, yfp, nullptr, TOKENS, DM, DM);

    // per-row rms scale of y
    stats_kernel<<<TOKENS, 256>>>(y16, rvec);

    // W1: ff1 = relu(y@W1) * r   (== relu((y*r)@W1))
    gemm_h<M_W1><<<g_di, 128, GEMM_DSM>>>(
        y16, w1t, w1t, w1t, f16, f16, f16, nullptr, nullptr, rvec, TOKENS, DI, DM);

    // W2: ff2 (fp16)
    gemm_h<M_W2><<<g_dm, 128, GEMM_DSM>>>(
        f16, w2t, w2t, w2t, t16, t16, t16, nullptr, nullptr, nullptr, TOKENS, DM, DI);

    // out = rmsnorm(y*r + ff2)
    final_kernel<<<TOKENS, 256>>>(yfp, rvec, t16, out);
}

// round 16
// speedup vs baseline: 1.0204x; 1.0204x over previous
#include <cuda_runtime.h>
#include <cuda_fp16.h>
#include <cstdint>
#include <math.h>

// Problem constants
#define TOKENS 8192      // B*S = 4*2048
#define DM     1024
#define DI     4096
#define SEQ    2048
#define BATCH  4
#define NH     16
#define HD     64
#define RMS_EPS 1.1920929e-07f
#define LOG2E  1.44269504088896f

// ---------------- scratch (no allocations allowed) ----------------
__device__ __half g_x16 [TOKENS * DM];
__device__ __half g_q16 [TOKENS * DM];
__device__ __half g_k16 [TOKENS * DM];
__device__ __half g_v16 [TOKENS * DM];
__device__ __half g_c16 [TOKENS * DM];   // ctx fp16
__device__ __half g_h16 [TOKENS * DM];
__device__ __half g_f16 [TOKENS * DI];   // ff1 fp16
__device__ float  g_t0  [TOKENS * DM];   // fp32 residual branches
__device__ float  g_h   [TOKENS * DM];
// transposed fp16 weights [N][K]
__device__ __half g_wqt[DM * DM];
__device__ __half g_wkt[DM * DM];
__device__ __half g_wvt[DM * DM];
__device__ __half g_wot[DM * DM];
__device__ __half g_w1t[DI * DM];
__device__ __half g_w2t[DM * DI];

// ================= helpers =================
__device__ __forceinline__ uint32_t smem_u32(const void* p) {
    return (uint32_t)__cvta_generic_to_shared(p);
}
__device__ __forceinline__ void cp16(uint32_t s, const void* g) {
    asm volatile("cp.async.cg.shared.global [%0], [%1], 16;\n"
                 :: "r"(s), "l"(__cvta_generic_to_global(g)) : "memory");
}
__device__ __forceinline__ void cp_commit() {
    asm volatile("cp.async.commit_group;\n" ::: "memory");
}
template<int N>
__device__ __forceinline__ void cp_wait() {
    asm volatile("cp.async.wait_group %0;\n" :: "n"(N) : "memory");
}
__device__ __forceinline__ void mma_f16_16n8k16(float* c, const uint32_t* a,
                                                uint32_t b0, uint32_t b1) {
    asm volatile(
        "mma.sync.aligned.m16n8k16.row.col.f32.f16.f16.f32 "
        "{%0,%1,%2,%3}, {%4,%5,%6,%7}, {%8,%9}, {%0,%1,%2,%3};"
        : "+f"(c[0]), "+f"(c[1]), "+f"(c[2]), "+f"(c[3])
        : "r"(a[0]), "r"(a[1]), "r"(a[2]), "r"(a[3]), "r"(b0), "r"(b1));
}
__device__ __forceinline__ void ldsm_x4(uint32_t& r0, uint32_t& r1, uint32_t& r2,
                                        uint32_t& r3, uint32_t addr) {
    asm volatile("ldmatrix.sync.aligned.m8n8.x4.shared.b16 {%0,%1,%2,%3}, [%4];"
                 : "=r"(r0), "=r"(r1), "=r"(r2), "=r"(r3) : "r"(addr));
}
__device__ __forceinline__ void ldsm_x4_t(uint32_t& r0, uint32_t& r1, uint32_t& r2,
                                          uint32_t& r3, uint32_t addr) {
    asm volatile("ldmatrix.sync.aligned.m8n8.x4.trans.shared.b16 {%0,%1,%2,%3}, [%4];"
                 : "=r"(r0), "=r"(r1), "=r"(r2), "=r"(r3) : "r"(addr));
}
__device__ __forceinline__ float ex2(float x) {
    float y;
    asm("ex2.approx.f32 %0, %1;" : "=f"(y) : "f"(x));
    return y;
}
__device__ __forceinline__ uint32_t ldh32(const __half* p) {
    return *(const uint32_t*)p;
}
__device__ __forceinline__ uint32_t packh2(float a, float b) {
    __half2 h = __floats2half2_rn(a, b);
    return *(uint32_t*)&h;
}

// ================= pre-pass: weight transpose fp32[R][C] -> fp16[C][R] =================
__global__ __launch_bounds__(256)
void trans_cvt_kernel(const float* Wq, const float* Wk, const float* Wv,
                      const float* Wo, const float* W1, const float* W2,
                      __half* oq, __half* ok, __half* ov,
                      __half* oo, __half* o1, __half* o2)
{
    const float* in; __half* out; int R, C; float scale = 1.f;
    switch (blockIdx.z) {
        case 0: in = Wq; out = oq; R = DM; C = DM; scale = 0.125f * LOG2E; break;
        case 1: in = Wk; out = ok; R = DM; C = DM; break;
        case 2: in = Wv; out = ov; R = DM; C = DM; break;
        case 3: in = Wo; out = oo; R = DM; C = DM; break;
        case 4: in = W1; out = o1; R = DM; C = DI; break;
        default: in = W2; out = o2; R = DI; C = DM; break;
    }
    int c0 = blockIdx.x * 32, r0 = blockIdx.y * 32;
    if (c0 >= C || r0 >= R) return;
    __shared__ float t[32][33];
    int x = threadIdx.x & 31, y = (threadIdx.x >> 5) * 4;
    #pragma unroll
    for (int dy = 0; dy < 4; dy++)
        t[y + dy][x] = in[(size_t)(r0 + y + dy) * C + c0 + x];
    __syncthreads();
    #pragma unroll
    for (int dy = 0; dy < 4; dy++)
        out[(size_t)(c0 + y + dy) * R + r0 + x] = __float2half_rn(t[x][y + dy] * scale);
}

__global__ __launch_bounds__(256)
void cvt16_kernel(const float4* __restrict__ in, __half2* __restrict__ out, int n4)
{
    int i = blockIdx.x * 256 + threadIdx.x;
    if (i < n4) {
        float4 v = in[i];
        out[2 * i]     = __floats2half2_rn(v.x, v.y);
        out[2 * i + 1] = __floats2half2_rn(v.z, v.w);
    }
}

// ================= fp16 mma.sync GEMM (BK=64, warp tile 64x64, 128 thr) =================
// C[M,N] = A[M,K] @ Bt[N,K]^T (+ReLU). CTA 128x128, 4 warps in 2x2 grid.  (R14 proven)
#define HSTR 72
#define H_TILE (128 * HSTR)
#define GEMM_DSM ((4 * H_TILE) * 2)                // 73728 B

template<bool RELU, bool HALF_OUT>
__global__ __launch_bounds__(128, 2)
void gemm_h(const __half* __restrict__ A,
            const __half* __restrict__ B0, const __half* __restrict__ B1,
            const __half* __restrict__ B2,
            void* __restrict__ C0, void* __restrict__ C1, void* __restrict__ C2,
            int M, int N, int K)
{
    extern __shared__ __half hs[];
    __half* As = hs;
    __half* Bs = hs + 2 * H_TILE;

    const __half* B = (blockIdx.z == 0) ? B0 : (blockIdx.z == 1 ? B1 : B2);
    void*         C = (blockIdx.z == 0) ? C0 : (blockIdx.z == 1 ? C1 : C2);

    const int tid  = threadIdx.x;
    const int lane = tid & 31;
    const int warp = tid >> 5;
    const int warpM = warp & 1;
    const int warpN = warp >> 1;
    const int grp = lane >> 2;
    const int qd  = lane & 3;
    const int li  = lane & 7;
    const int sel = lane >> 3;
    const int rowBase = blockIdx.y * 128;
    const int colBase = blockIdx.x * 128;
    const int numK = K >> 6;

    const uint32_t sAu = smem_u32(As);
    const uint32_t sBu = smem_u32(Bs);

    const int aOff = (warpM * 64 + (sel & 1) * 8 + li) * HSTR + (sel >> 1) * 8;
    const int bOff = (warpN * 64 + (sel >> 1) * 8 + li) * HSTR + (sel & 1) * 8;

    float acc[4][8][4];
    #pragma unroll
    for (int i = 0; i < 4; i++)
        #pragma unroll
        for (int j = 0; j < 8; j++)
            #pragma unroll
            for (int e = 0; e < 4; e++) acc[i][j][e] = 0.f;

    auto load_stage = [&](int chunk, int stage) {
        const int k0 = chunk << 6;
        const uint32_t dA = sAu + stage * H_TILE * 2;
        const uint32_t dB = sBu + stage * H_TILE * 2;
        #pragma unroll
        for (int it = 0; it < 8; it++) {
            int i = tid + it * 128;
            int r = i >> 3, c8 = i & 7;
            cp16(dA + (r * HSTR + c8 * 8) * 2,
                 A + (size_t)(rowBase + r) * K + k0 + c8 * 8);
        }
        #pragma unroll
        for (int it = 0; it < 8; it++) {
            int i = tid + it * 128;
            int r = i >> 3, c8 = i & 7;
            cp16(dB + (r * HSTR + c8 * 8) * 2,
                 B + (size_t)(colBase + r) * K + k0 + c8 * 8);
        }
    };

    load_stage(0, 0);
    cp_commit();

    for (int i = 0; i < numK; i++) {
        if (i + 1 < numK) {
            load_stage(i + 1, (i + 1) & 1);
            cp_commit();
            cp_wait<1>();
        } else {
            cp_wait<0>();
        }
        __syncthreads();

        const uint32_t pAu = sAu + (i & 1) * H_TILE * 2 + aOff * 2;
        const uint32_t pBu = sBu + (i & 1) * H_TILE * 2 + bOff * 2;

        #pragma unroll
        for (int ks = 0; ks < 4; ks++) {
            const int k0 = ks * 16;
            uint32_t afr[4][4], bfr[4][4];
            #pragma unroll
            for (int mt = 0; mt < 4; mt++)
                ldsm_x4(afr[mt][0], afr[mt][1], afr[mt][2], afr[mt][3],
                        pAu + (mt * 16 * HSTR + k0) * 2);
            #pragma unroll
            for (int np = 0; np < 4; np++)
                ldsm_x4(bfr[np][0], bfr[np][1], bfr[np][2], bfr[np][3],
                        pBu + (np * 16 * HSTR + k0) * 2);
            #pragma unroll
            for (int mt = 0; mt < 4; mt++) {
                #pragma unroll
                for (int np = 0; np < 4; np++) {
                    mma_f16_16n8k16(acc[mt][2 * np    ], afr[mt], bfr[np][0], bfr[np][1]);
                    mma_f16_16n8k16(acc[mt][2 * np + 1], afr[mt], bfr[np][2], bfr[np][3]);
                }
            }
        }
        __syncthreads();
    }

    // epilogue: warp writes 64x64
    #pragma unroll
    for (int mt = 0; mt < 4; mt++) {
        int r0 = rowBase + warpM * 64 + mt * 16 + grp;
        #pragma unroll
        for (int nt = 0; nt < 8; nt++) {
            int c0 = colBase + warpN * 64 + nt * 8 + qd * 2;
            float v[4] = {acc[mt][nt][0], acc[mt][nt][1], acc[mt][nt][2], acc[mt][nt][3]};
            if (RELU) {
                #pragma unroll
                for (int e = 0; e < 4; e++) v[e] = fmaxf(v[e], 0.f);
            }
            if (HALF_OUT) {
                __half* Ch = (__half*)C;
                *(__half2*)&Ch[(size_t)(r0    ) * N + c0] = __floats2half2_rn(v[0], v[1]);
                *(__half2*)&Ch[(size_t)(r0 + 8) * N + c0] = __floats2half2_rn(v[2], v[3]);
            } else {
                float* Cf = (float*)C;
                *(float2*)&Cf[(size_t)(r0    ) * N + c0] = make_float2(v[0], v[1]);
                *(float2*)&Cf[(size_t)(r0 + 8) * N + c0] = make_float2(v[2], v[3]);
            }
        }
    }
}

// ================= fp16 flash attention (no-max softmax, register P, kv-tile 128) =================
// 128-kv-row tiles double-buffered; each tile computed as two sequential 64-col
// chunks (same register footprint as kv-64) -> HALF the __syncthreads, double
// prefetch distance.
#define AKST 72
#define ATT_K_TILE (128 * AKST)
#define ATT_VS_OFF (2 * ATT_K_TILE)
#define ATT_DSM ((4 * ATT_K_TILE) * 2)    // 73728 B
#define NKT2 (SEQ / 128)

__global__ __launch_bounds__(256, 2)
void attn_h_kernel(const __half* __restrict__ Q, const __half* __restrict__ K,
                   const __half* __restrict__ V, __half* __restrict__ O)
{
    extern __shared__ __half smh[];
    __half* Ks = smh;
    __half* Vs = smh + ATT_VS_OFF;

    const int b  = blockIdx.z;
    const int hh = blockIdx.y;
    const int qt = blockIdx.x;
    const int tid = threadIdx.x;
    const int lane = tid & 31;
    const int w = tid >> 5;
    const int grp = lane >> 2;
    const int qd  = lane & 3;
    const int li  = lane & 7;
    const int sel = lane >> 3;

    const size_t base = ((size_t)b * SEQ) * DM + (size_t)hh * HD;
    const __half* Kg = K + base;
    const __half* Vg = V + base;

    // ---- Q fragments (already scaled by 0.125*log2e via Wq) ----
    uint32_t qa[4][4];
    {
        const __half* q0 = Q + base + (size_t)(qt * 128 + w * 16 + grp) * DM;
        const __half* q8 = q0 + 8 * (size_t)DM;
        #pragma unroll
        for (int ks = 0; ks < 4; ks++) {
            qa[ks][0] = ldh32(&q0[ks * 16 + 2 * qd    ]);
            qa[ks][1] = ldh32(&q8[ks * 16 + 2 * qd    ]);
            qa[ks][2] = ldh32(&q0[ks * 16 + 2 * qd + 8]);
            qa[ks][3] = ldh32(&q8[ks * 16 + 2 * qd + 8]);
        }
    }

    float o[8][4];
    #pragma unroll
    for (int i = 0; i < 8; i++)
        #pragma unroll
        for (int e = 0; e < 4; e++) o[i][e] = 0.f;
    float l0p = 0.f, l1p = 0.f;

    const uint32_t ksU = smem_u32(Ks);
    const uint32_t vsU = smem_u32(Vs);
    const int kOff = ((sel >> 1) * 8 + li) * AKST + (sel & 1) * 8;
    const int vOff = ((sel & 1) * 8 + li) * AKST + (sel >> 1) * 8;

    // load one 128-kv-row tile (K + V)
    auto load_tile = [&](int t, int buf) {
        const __half* Kn = Kg + (size_t)t * 128 * DM;
        const __half* Vn = Vg + (size_t)t * 128 * DM;
        uint32_t kb = ksU + buf * ATT_K_TILE * 2;
        uint32_t vb = vsU + buf * ATT_K_TILE * 2;
        #pragma unroll
        for (int it = 0; it < 4; it++) {
            int i = tid + it * 256;
            int r = i >> 3, c8 = i & 7;
            cp16(kb + (r * AKST + c8 * 8) * 2, Kn + (size_t)r * DM + c8 * 8);
        }
        #pragma unroll
        for (int it = 0; it < 4; it++) {
            int i = tid + it * 256;
            int r = i >> 3, c8 = i & 7;
            cp16(vb + (r * AKST + c8 * 8) * 2, Vn + (size_t)r * DM + c8 * 8);
        }
    };

    load_tile(0, 0);
    cp_commit();

    for (int kt = 0; kt < NKT2; kt++) {
        cp_wait<0>();
        __syncthreads();

        if (kt + 1 < NKT2) {
            load_tile(kt + 1, (kt + 1) & 1);
            cp_commit();
        }

        const uint32_t tileK = ksU + (kt & 1) * ATT_K_TILE * 2;
        const uint32_t tileV = vsU + (kt & 1) * ATT_K_TILE * 2;

        #pragma unroll
        for (int half = 0; half < 2; half++) {
            const uint32_t kbU = tileK + (half * 64 * AKST + kOff) * 2;
            const uint32_t vbU = tileV + (half * 64 * AKST + vOff) * 2;

            // ---- S = Qs @ K^T (64 kv cols) ----
            float s[8][4];
            #pragma unroll
            for (int nt = 0; nt < 8; nt++)
                #pragma unroll
                for (int e = 0; e < 4; e++) s[nt][e] = 0.f;

            #pragma unroll
            for (int ks = 0; ks < 4; ks++) {
                #pragma unroll
                for (int ntp = 0; ntp < 4; ntp++) {
                    uint32_t b0, b1, b2, b3;
                    ldsm_x4(b0, b1, b2, b3, kbU + (ntp * 16 * AKST + ks * 16) * 2);
                    mma_f16_16n8k16(s[2 * ntp    ], qa[ks], b0, b1);
                    mma_f16_16n8k16(s[2 * ntp + 1], qa[ks], b2, b3);
                }
            }

            // ---- softmax numerator (no max subtraction) ----
            uint32_t pa0[8], pa1[8];
            #pragma unroll
            for (int nt = 0; nt < 8; nt++) {
                float e00 = ex2(s[nt][0]), e01 = ex2(s[nt][1]);
                float e10 = ex2(s[nt][2]), e11 = ex2(s[nt][3]);
                l0p += e00 + e01;
                l1p += e10 + e11;
                pa0[nt] = packh2(e00, e01);
                pa1[nt] = packh2(e10, e11);
            }

            // ---- O += P @ V ----
            #pragma unroll
            for (int ks2 = 0; ks2 < 4; ks2++) {
                uint32_t pa[4] = {pa0[2 * ks2], pa1[2 * ks2],
                                  pa0[2 * ks2 + 1], pa1[2 * ks2 + 1]};
                #pragma unroll
                for (int dp = 0; dp < 4; dp++) {
                    uint32_t b0, b1, b2, b3;
                    ldsm_x4_t(b0, b1, b2, b3, vbU + (ks2 * 16 * AKST + dp * 16) * 2);
                    mma_f16_16n8k16(o[2 * dp    ], pa, b0, b1);
                    mma_f16_16n8k16(o[2 * dp + 1], pa, b2, b3);
                }
            }
        }
    }

    // ---- final l reduction + epilogue ----
    l0p += __shfl_xor_sync(0xffffffffu, l0p, 1);
    l0p += __shfl_xor_sync(0xffffffffu, l0p, 2);
    l1p += __shfl_xor_sync(0xffffffffu, l1p, 1);
    l1p += __shfl_xor_sync(0xffffffffu, l1p, 2);
    float i0 = 1.f / l0p, i1 = 1.f / l1p;
    __half* o0 = O + base + (size_t)(qt * 128 + w * 16 + grp) * DM;
    __half* o8 = o0 + 8 * (size_t)DM;
    #pragma unroll
    for (int nt2 = 0; nt2 < 8; nt2++) {
        *(__half2*)&o0[nt2 * 8 + 2 * qd] = __floats2half2_rn(o[nt2][0] * i0, o[nt2][1] * i0);
        *(__half2*)&o8[nt2 * 8 + 2 * qd] = __floats2half2_rn(o[nt2][2] * i1, o[nt2][3] * i1);
    }
}

// ---------------- fused residual add + RMSNorm ----------------
template<bool EMIT16>
__global__ __launch_bounds__(256)
void add_rmsnorm_kernel(const float* __restrict__ A, const float* __restrict__ B,
                        float* __restrict__ Out, __half* __restrict__ Out16)
{
    __shared__ float red[8];
    const int row = blockIdx.x;
    const int t = threadIdx.x;

    float4 va = ((const float4*)(A + (size_t)row * DM))[t];
    float4 vb = ((const float4*)(B + (size_t)row * DM))[t];
    float4 y = make_float4(va.x + vb.x, va.y + vb.y, va.z + vb.z, va.w + vb.w);
    float ss = y.x * y.x + y.y * y.y + y.z * y.z + y.w * y.w;

    #pragma unroll
    for (int off = 16; off >= 1; off >>= 1)
        ss += __shfl_xor_sync(0xffffffffu, ss, off);
    if ((t & 31) == 0) red[t >> 5] = ss;
    __syncthreads();

    float tot = 0.f;
    #pragma unroll
    for (int w = 0; w < 8; w++) tot += red[w];

    float inv = rsqrtf(tot * (1.0f / DM) + RMS_EPS);
    float4 r = make_float4(y.x * inv, y.y * inv, y.z * inv, y.w * inv);
    ((float4*)(Out + (size_t)row * DM))[t] = r;
    if (EMIT16) {
        __half2* p = (__half2*)(Out16 + (size_t)row * DM);
        p[2 * t]     = __floats2half2_rn(r.x, r.y);
        p[2 * t + 1] = __floats2half2_rn(r.z, r.w);
    }
}

// ---------------- launch ----------------
extern "C" void kernel_launch(void* const* d_in, const int* in_sizes, int n_in,
                              void* d_out, int out_size)
{
    const float* x  = (const float*)d_in[0];
    const float* Wq = (const float*)d_in[1];
    const float* Wk = (const float*)d_in[2];
    const float* Wv = (const float*)d_in[3];
    const float* Wo = (const float*)d_in[4];
    const float* W1 = (const float*)d_in[5];
    const float* W2 = (const float*)d_in[6];
    float* out = (float*)d_out;

    __half *x16, *q16, *k16, *v16, *c16, *h16, *f16;
    __half *wqt, *wkt, *wvt, *wot, *w1t, *w2t;
    float *t0, *h;
    cudaGetSymbolAddress((void**)&x16, g_x16);
    cudaGetSymbolAddress((void**)&q16, g_q16);
    cudaGetSymbolAddress((void**)&k16, g_k16);
    cudaGetSymbolAddress((void**)&v16, g_v16);
    cudaGetSymbolAddress((void**)&c16, g_c16);
    cudaGetSymbolAddress((void**)&h16, g_h16);
    cudaGetSymbolAddress((void**)&f16, g_f16);
    cudaGetSymbolAddress((void**)&t0,  g_t0);
    cudaGetSymbolAddress((void**)&h,   g_h);
    cudaGetSymbolAddress((void**)&wqt, g_wqt);
    cudaGetSymbolAddress((void**)&wkt, g_wkt);
    cudaGetSymbolAddress((void**)&wvt, g_wvt);
    cudaGetSymbolAddress((void**)&wot, g_wot);
    cudaGetSymbolAddress((void**)&w1t, g_w1t);
    cudaGetSymbolAddress((void**)&w2t, g_w2t);

    cudaFuncSetAttribute(attn_h_kernel, cudaFuncAttributeMaxDynamicSharedMemorySize,
                         ATT_DSM);
    cudaFuncSetAttribute((const void*)gemm_h<false, true>,
                         cudaFuncAttributeMaxDynamicSharedMemorySize, GEMM_DSM);
    cudaFuncSetAttribute((const void*)gemm_h<false, false>,
                         cudaFuncAttributeMaxDynamicSharedMemorySize, GEMM_DSM);
    cudaFuncSetAttribute((const void*)gemm_h<true, true>,
                         cudaFuncAttributeMaxDynamicSharedMemorySize, GEMM_DSM);

    // ---- pre-pass ----
    trans_cvt_kernel<<<dim3(DI / 32, DI / 32, 6), 256>>>(
        Wq, Wk, Wv, Wo, W1, W2, wqt, wkt, wvt, wot, w1t, w2t);
    cvt16_kernel<<<(TOKENS * DM / 4 + 255) / 256, 256>>>(
        (const float4*)x, (__half2*)x16, TOKENS * DM / 4);

    dim3 g_qkv(DM / 128, TOKENS / 128, 3);
    dim3 g_dm (DM / 128, TOKENS / 128, 1);
    dim3 g_di (DI / 128, TOKENS / 128, 1);

    gemm_h<false, true><<<g_qkv, 128, GEMM_DSM>>>(
        x16, wqt, wkt, wvt, q16, k16, v16, TOKENS, DM, DM);

    attn_h_kernel<<<dim3(SEQ / 128, NH, BATCH), 256, ATT_DSM>>>(q16, k16, v16, c16);

    gemm_h<false, false><<<g_dm, 128, GEMM_DSM>>>(
        c16, wot, wot, wot, t0, t0, t0, TOKENS, DM, DM);
    add_rmsnorm_kernel<true><<<TOKENS, 256>>>(x, t0, h, h16);

    gemm_h<true, true><<<g_di, 128, GEMM_DSM>>>(
        h16, w1t, w1t, w1t, f16, f16, f16, TOKENS, DI, DM);
    gemm_h<false, false><<<g_dm, 128, GEMM_DSM>>>(
        f16, w2t, w2t, w2t, t0, t0, t0, TOKENS, DM, DI);
    add_rmsnorm_kernel<false><<<TOKENS, 256>>>(h, t0, out, (__half*)nullptr);
}

// round 17
// speedup vs baseline: 1.0729x; 1.0514x over previous
#include <cuda_runtime.h>
#include <cuda_fp16.h>
#include <cstdint>
#include <math.h>

// Problem constants
#define TOKENS 8192      // B*S = 4*2048
#define DM     1024
#define DI     4096
#define SEQ    2048
#define BATCH  4
#define NH     16
#define HD     64
#define RMS_EPS 1.1920929e-07f
#define LOG2E  1.44269504088896f

// ---------------- scratch (no allocations allowed) ----------------
__device__ __half g_x16 [TOKENS * DM];
__device__ __half g_q16 [TOKENS * DM];
__device__ __half g_k16 [TOKENS * DM];
__device__ __half g_v16 [TOKENS * DM];
__device__ __half g_c16 [TOKENS * DM];   // ctx fp16
__device__ __half g_h16 [TOKENS * DM];
__device__ __half g_f16 [TOKENS * DI];   // ff1 fp16
__device__ float  g_t0  [TOKENS * DM];   // fp32 residual branches
__device__ float  g_h   [TOKENS * DM];
// transposed fp16 weights [N][K]
__device__ __half g_wqt[DM * DM];
__device__ __half g_wkt[DM * DM];
__device__ __half g_wvt[DM * DM];
__device__ __half g_wot[DM * DM];
__device__ __half g_w1t[DI * DM];
__device__ __half g_w2t[DM * DI];

// ================= helpers =================
__device__ __forceinline__ uint32_t smem_u32(const void* p) {
    return (uint32_t)__cvta_generic_to_shared(p);
}
__device__ __forceinline__ void cp16(uint32_t s, const void* g) {
    asm volatile("cp.async.cg.shared.global [%0], [%1], 16;\n"
                 :: "r"(s), "l"(__cvta_generic_to_global(g)) : "memory");
}
__device__ __forceinline__ void cp_commit() {
    asm volatile("cp.async.commit_group;\n" ::: "memory");
}
template<int N>
__device__ __forceinline__ void cp_wait() {
    asm volatile("cp.async.wait_group %0;\n" :: "n"(N) : "memory");
}
__device__ __forceinline__ void mma_f16_16n8k16(float* c, const uint32_t* a,
                                                uint32_t b0, uint32_t b1) {
    asm volatile(
        "mma.sync.aligned.m16n8k16.row.col.f32.f16.f16.f32 "
        "{%0,%1,%2,%3}, {%4,%5,%6,%7}, {%8,%9}, {%0,%1,%2,%3};"
        : "+f"(c[0]), "+f"(c[1]), "+f"(c[2]), "+f"(c[3])
        : "r"(a[0]), "r"(a[1]), "r"(a[2]), "r"(a[3]), "r"(b0), "r"(b1));
}
__device__ __forceinline__ void ldsm_x4(uint32_t& r0, uint32_t& r1, uint32_t& r2,
                                        uint32_t& r3, uint32_t addr) {
    asm volatile("ldmatrix.sync.aligned.m8n8.x4.shared.b16 {%0,%1,%2,%3}, [%4];"
                 : "=r"(r0), "=r"(r1), "=r"(r2), "=r"(r3) : "r"(addr));
}
__device__ __forceinline__ void ldsm_x4_t(uint32_t& r0, uint32_t& r1, uint32_t& r2,
                                          uint32_t& r3, uint32_t addr) {
    asm volatile("ldmatrix.sync.aligned.m8n8.x4.trans.shared.b16 {%0,%1,%2,%3}, [%4];"
                 : "=r"(r0), "=r"(r1), "=r"(r2), "=r"(r3) : "r"(addr));
}
__device__ __forceinline__ float ex2(float x) {
    float y;
    asm("ex2.approx.f32 %0, %1;" : "=f"(y) : "f"(x));
    return y;
}
__device__ __forceinline__ uint32_t ldh32(const __half* p) {
    return *(const uint32_t*)p;
}
__device__ __forceinline__ uint32_t packh2(float a, float b) {
    __half2 h = __floats2half2_rn(a, b);
    return *(uint32_t*)&h;
}

// ================= pre-pass: weight transpose, exact 1D tile grid =================
// 12288 tiles total: 4 x (DM*DM: 1024 tiles) + W1 (4096) + W2 (4096).
#define N_TILE_DM   1024          // (DM/32)*(DM/32)
#define N_TILE_BIG  4096          // (DI/32)*(DM/32)
#define N_TILES_ALL (4 * N_TILE_DM + 2 * N_TILE_BIG)

__global__ __launch_bounds__(256)
void trans_cvt_kernel(const float* Wq, const float* Wk, const float* Wv,
                      const float* Wo, const float* W1, const float* W2,
                      __half* oq, __half* ok, __half* ov,
                      __half* oo, __half* o1, __half* o2)
{
    int b = blockIdx.x;
    const float* in; __half* out; int R, C, t; float scale = 1.f;
    if (b < 4 * N_TILE_DM) {
        int m = b >> 10;            // matrix 0..3
        t = b & (N_TILE_DM - 1);
        R = DM; C = DM;
        switch (m) {
            case 0: in = Wq; out = oq; scale = 0.125f * LOG2E; break;
            case 1: in = Wk; out = ok; break;
            case 2: in = Wv; out = ov; break;
            default: in = Wo; out = oo; break;
        }
    } else if (b < 4 * N_TILE_DM + N_TILE_BIG) {
        t = b - 4 * N_TILE_DM;
        in = W1; out = o1; R = DM; C = DI;
    } else {
        t = b - 4 * N_TILE_DM - N_TILE_BIG;
        in = W2; out = o2; R = DI; C = DM;
    }
    const int tilesC = C >> 5;
    int c0 = (t % tilesC) * 32, r0 = (t / tilesC) * 32;

    __shared__ float tl[32][33];
    int x = threadIdx.x & 31, y = (threadIdx.x >> 5) * 4;
    #pragma unroll
    for (int dy = 0; dy < 4; dy++)
        tl[y + dy][x] = in[(size_t)(r0 + y + dy) * C + c0 + x];
    __syncthreads();
    #pragma unroll
    for (int dy = 0; dy < 4; dy++)
        out[(size_t)(c0 + y + dy) * R + r0 + x] = __float2half_rn(tl[x][y + dy] * scale);
}

__global__ __launch_bounds__(256)
void cvt16_kernel(const float4* __restrict__ in, __half2* __restrict__ out, int n4)
{
    int i = blockIdx.x * 256 + threadIdx.x;
    if (i < n4) {
        float4 v = in[i];
        out[2 * i]     = __floats2half2_rn(v.x, v.y);
        out[2 * i + 1] = __floats2half2_rn(v.z, v.w);
    }
}

// ================= fp16 mma.sync GEMM (BK=64, warp tile 64x64, 128 thr) — R14 proven =================
#define HSTR 72
#define H_TILE (128 * HSTR)
#define GEMM_DSM ((4 * H_TILE) * 2)                // 73728 B

template<bool RELU, bool HALF_OUT>
__global__ __launch_bounds__(128, 2)
void gemm_h(const __half* __restrict__ A,
            const __half* __restrict__ B0, const __half* __restrict__ B1,
            const __half* __restrict__ B2,
            void* __restrict__ C0, void* __restrict__ C1, void* __restrict__ C2,
            int M, int N, int K)
{
    extern __shared__ __half hs[];
    __half* As = hs;
    __half* Bs = hs + 2 * H_TILE;

    const __half* B = (blockIdx.z == 0) ? B0 : (blockIdx.z == 1 ? B1 : B2);
    void*         C = (blockIdx.z == 0) ? C0 : (blockIdx.z == 1 ? C1 : C2);

    const int tid  = threadIdx.x;
    const int lane = tid & 31;
    const int warp = tid >> 5;
    const int warpM = warp & 1;
    const int warpN = warp >> 1;
    const int grp = lane >> 2;
    const int qd  = lane & 3;
    const int li  = lane & 7;
    const int sel = lane >> 3;
    const int rowBase = blockIdx.y * 128;
    const int colBase = blockIdx.x * 128;
    const int numK = K >> 6;

    const uint32_t sAu = smem_u32(As);
    const uint32_t sBu = smem_u32(Bs);

    const int aOff = (warpM * 64 + (sel & 1) * 8 + li) * HSTR + (sel >> 1) * 8;
    const int bOff = (warpN * 64 + (sel >> 1) * 8 + li) * HSTR + (sel & 1) * 8;

    float acc[4][8][4];
    #pragma unroll
    for (int i = 0; i < 4; i++)
        #pragma unroll
        for (int j = 0; j < 8; j++)
            #pragma unroll
            for (int e = 0; e < 4; e++) acc[i][j][e] = 0.f;

    auto load_stage = [&](int chunk, int stage) {
        const int k0 = chunk << 6;
        const uint32_t dA = sAu + stage * H_TILE * 2;
        const uint32_t dB = sBu + stage * H_TILE * 2;
        #pragma unroll
        for (int it = 0; it < 8; it++) {
            int i = tid + it * 128;
            int r = i >> 3, c8 = i & 7;
            cp16(dA + (r * HSTR + c8 * 8) * 2,
                 A + (size_t)(rowBase + r) * K + k0 + c8 * 8);
        }
        #pragma unroll
        for (int it = 0; it < 8; it++) {
            int i = tid + it * 128;
            int r = i >> 3, c8 = i & 7;
            cp16(dB + (r * HSTR + c8 * 8) * 2,
                 B + (size_t)(colBase + r) * K + k0 + c8 * 8);
        }
    };

    load_stage(0, 0);
    cp_commit();

    for (int i = 0; i < numK; i++) {
        if (i + 1 < numK) {
            load_stage(i + 1, (i + 1) & 1);
            cp_commit();
            cp_wait<1>();
        } else {
            cp_wait<0>();
        }
        __syncthreads();

        const uint32_t pAu = sAu + (i & 1) * H_TILE * 2 + aOff * 2;
        const uint32_t pBu = sBu + (i & 1) * H_TILE * 2 + bOff * 2;

        #pragma unroll
        for (int ks = 0; ks < 4; ks++) {
            const int k0 = ks * 16;
            uint32_t afr[4][4], bfr[4][4];
            #pragma unroll
            for (int mt = 0; mt < 4; mt++)
                ldsm_x4(afr[mt][0], afr[mt][1], afr[mt][2], afr[mt][3],
                        pAu + (mt * 16 * HSTR + k0) * 2);
            #pragma unroll
            for (int np = 0; np < 4; np++)
                ldsm_x4(bfr[np][0], bfr[np][1], bfr[np][2], bfr[np][3],
                        pBu + (np * 16 * HSTR + k0) * 2);
            #pragma unroll
            for (int mt = 0; mt < 4; mt++) {
                #pragma unroll
                for (int np = 0; np < 4; np++) {
                    mma_f16_16n8k16(acc[mt][2 * np    ], afr[mt], bfr[np][0], bfr[np][1]);
                    mma_f16_16n8k16(acc[mt][2 * np + 1], afr[mt], bfr[np][2], bfr[np][3]);
                }
            }
        }
        __syncthreads();
    }

    // epilogue: warp writes 64x64
    #pragma unroll
    for (int mt = 0; mt < 4; mt++) {
        int r0 = rowBase + warpM * 64 + mt * 16 + grp;
        #pragma unroll
        for (int nt = 0; nt < 8; nt++) {
            int c0 = colBase + warpN * 64 + nt * 8 + qd * 2;
            float v[4] = {acc[mt][nt][0], acc[mt][nt][1], acc[mt][nt][2], acc[mt][nt][3]};
            if (RELU) {
                #pragma unroll
                for (int e = 0; e < 4; e++) v[e] = fmaxf(v[e], 0.f);
            }
            if (HALF_OUT) {
                __half* Ch = (__half*)C;
                *(__half2*)&Ch[(size_t)(r0    ) * N + c0] = __floats2half2_rn(v[0], v[1]);
                *(__half2*)&Ch[(size_t)(r0 + 8) * N + c0] = __floats2half2_rn(v[2], v[3]);
            } else {
                float* Cf = (float*)C;
                *(float2*)&Cf[(size_t)(r0    ) * N + c0] = make_float2(v[0], v[1]);
                *(float2*)&Cf[(size_t)(r0 + 8) * N + c0] = make_float2(v[2], v[3]);
            }
        }
    }
}

// ================= fp16 flash attention (no-max softmax, register P) — R14 proven =================
#define AKST 72
#define ATT_K_TILE (64 * AKST)
#define ATT_VS_OFF (2 * ATT_K_TILE)
#define ATT_DSM ((4 * ATT_K_TILE) * 2)    // 36864 B
#define NKT (SEQ / 64)

__global__ __launch_bounds__(256, 2)
void attn_h_kernel(const __half* __restrict__ Q, const __half* __restrict__ K,
                   const __half* __restrict__ V, __half* __restrict__ O)
{
    extern __shared__ __half smh[];
    __half* Ks = smh;
    __half* Vs = smh + ATT_VS_OFF;

    const int b  = blockIdx.z;
    const int hh = blockIdx.y;
    const int qt = blockIdx.x;
    const int tid = threadIdx.x;
    const int lane = tid & 31;
    const int w = tid >> 5;
    const int grp = lane >> 2;
    const int qd  = lane & 3;
    const int li  = lane & 7;
    const int sel = lane >> 3;

    const size_t base = ((size_t)b * SEQ) * DM + (size_t)hh * HD;
    const __half* Kg = K + base;
    const __half* Vg = V + base;

    uint32_t qa[4][4];
    {
        const __half* q0 = Q + base + (size_t)(qt * 128 + w * 16 + grp) * DM;
        const __half* q8 = q0 + 8 * (size_t)DM;
        #pragma unroll
        for (int ks = 0; ks < 4; ks++) {
            qa[ks][0] = ldh32(&q0[ks * 16 + 2 * qd    ]);
            qa[ks][1] = ldh32(&q8[ks * 16 + 2 * qd    ]);
            qa[ks][2] = ldh32(&q0[ks * 16 + 2 * qd + 8]);
            qa[ks][3] = ldh32(&q8[ks * 16 + 2 * qd + 8]);
        }
    }

    float o[8][4];
    #pragma unroll
    for (int i = 0; i < 8; i++)
        #pragma unroll
        for (int e = 0; e < 4; e++) o[i][e] = 0.f;
    float l0p = 0.f, l1p = 0.f;

    const uint32_t ksU = smem_u32(Ks);
    const uint32_t vsU = smem_u32(Vs);
    const int kOff = ((sel >> 1) * 8 + li) * AKST + (sel & 1) * 8;
    const int vOff = ((sel & 1) * 8 + li) * AKST + (sel >> 1) * 8;

    auto load_tile = [&](int t, int buf) {
        const __half* Kn = Kg + (size_t)t * 64 * DM;
        const __half* Vn = Vg + (size_t)t * 64 * DM;
        uint32_t kb = ksU + buf * ATT_K_TILE * 2;
        uint32_t vb = vsU + buf * ATT_K_TILE * 2;
        #pragma unroll
        for (int it = 0; it < 2; it++) {
            int i = tid + it * 256;
            int r = i >> 3, c8 = i & 7;
            cp16(kb + (r * AKST + c8 * 8) * 2, Kn + (size_t)r * DM + c8 * 8);
        }
        #pragma unroll
        for (int it = 0; it < 2; it++) {
            int i = tid + it * 256;
            int r = i >> 3, c8 = i & 7;
            cp16(vb + (r * AKST + c8 * 8) * 2, Vn + (size_t)r * DM + c8 * 8);
        }
    };

    load_tile(0, 0);
    cp_commit();

    for (int kt = 0; kt < NKT; kt++) {
        cp_wait<0>();
        __syncthreads();

        if (kt + 1 < NKT) {
            load_tile(kt + 1, (kt + 1) & 1);
            cp_commit();
        }

        const uint32_t kbU = ksU + (kt & 1) * ATT_K_TILE * 2 + kOff * 2;
        const uint32_t vbU = vsU + (kt & 1) * ATT_K_TILE * 2 + vOff * 2;

        float s[8][4];
        #pragma unroll
        for (int nt = 0; nt < 8; nt++)
            #pragma unroll
            for (int e = 0; e < 4; e++) s[nt][e] = 0.f;

        #pragma unroll
        for (int ks = 0; ks < 4; ks++) {
            #pragma unroll
            for (int ntp = 0; ntp < 4; ntp++) {
                uint32_t b0, b1, b2, b3;
                ldsm_x4(b0, b1, b2, b3, kbU + (ntp * 16 * AKST + ks * 16) * 2);
                mma_f16_16n8k16(s[2 * ntp    ], qa[ks], b0, b1);
                mma_f16_16n8k16(s[2 * ntp + 1], qa[ks], b2, b3);
            }
        }

        uint32_t pa0[8], pa1[8];
        #pragma unroll
        for (int nt = 0; nt < 8; nt++) {
            float e00 = ex2(s[nt][0]), e01 = ex2(s[nt][1]);
            float e10 = ex2(s[nt][2]), e11 = ex2(s[nt][3]);
            l0p += e00 + e01;
            l1p += e10 + e11;
            pa0[nt] = packh2(e00, e01);
            pa1[nt] = packh2(e10, e11);
        }

        #pragma unroll
        for (int ks2 = 0; ks2 < 4; ks2++) {
            uint32_t pa[4] = {pa0[2 * ks2], pa1[2 * ks2], pa0[2 * ks2 + 1], pa1[2 * ks2 + 1]};
            #pragma unroll
            for (int dp = 0; dp < 4; dp++) {
                uint32_t b0, b1, b2, b3;
                ldsm_x4_t(b0, b1, b2, b3, vbU + (ks2 * 16 * AKST + dp * 16) * 2);
                mma_f16_16n8k16(o[2 * dp    ], pa, b0, b1);
                mma_f16_16n8k16(o[2 * dp + 1], pa, b2, b3);
            }
        }
    }

    l0p += __shfl_xor_sync(0xffffffffu, l0p, 1);
    l0p += __shfl_xor_sync(0xffffffffu, l0p, 2);
    l1p += __shfl_xor_sync(0xffffffffu, l1p, 1);
    l1p += __shfl_xor_sync(0xffffffffu, l1p, 2);
    float i0 = 1.f / l0p, i1 = 1.f / l1p;
    __half* o0 = O + base + (size_t)(qt * 128 + w * 16 + grp) * DM;
    __half* o8 = o0 + 8 * (size_t)DM;
    #pragma unroll
    for (int nt2 = 0; nt2 < 8; nt2++) {
        *(__half2*)&o0[nt2 * 8 + 2 * qd] = __floats2half2_rn(o[nt2][0] * i0, o[nt2][1] * i0);
        *(__half2*)&o8[nt2 * 8 + 2 * qd] = __floats2half2_rn(o[nt2][2] * i1, o[nt2][3] * i1);
    }
}

// ---------------- fused residual add + RMSNorm ----------------
template<bool EMIT16>
__global__ __launch_bounds__(256)
void add_rmsnorm_kernel(const float* __restrict__ A, const float* __restrict__ B,
                        float* __restrict__ Out, __half* __restrict__ Out16)
{
    __shared__ float red[8];
    const int row = blockIdx.x;
    const int t = threadIdx.x;

    float4 va = ((const float4*)(A + (size_t)row * DM))[t];
    float4 vb = ((const float4*)(B + (size_t)row * DM))[t];
    float4 y = make_float4(va.x + vb.x, va.y + vb.y, va.z + vb.z, va.w + vb.w);
    float ss = y.x * y.x + y.y * y.y + y.z * y.z + y.w * y.w;

    #pragma unroll
    for (int off = 16; off >= 1; off >>= 1)
        ss += __shfl_xor_sync(0xffffffffu, ss, off);
    if ((t & 31) == 0) red[t >> 5] = ss;
    __syncthreads();

    float tot = 0.f;
    #pragma unroll
    for (int w = 0; w < 8; w++) tot += red[w];

    float inv = rsqrtf(tot * (1.0f / DM) + RMS_EPS);
    float4 r = make_float4(y.x * inv, y.y * inv, y.z * inv, y.w * inv);
    ((float4*)(Out + (size_t)row * DM))[t] = r;
    if (EMIT16) {
        __half2* p = (__half2*)(Out16 + (size_t)row * DM);
        p[2 * t]     = __floats2half2_rn(r.x, r.y);
        p[2 * t + 1] = __floats2half2_rn(r.z, r.w);
    }
}

// ---------------- launch ----------------
extern "C" void kernel_launch(void* const* d_in, const int* in_sizes, int n_in,
                              void* d_out, int out_size)
{
    const float* x  = (const float*)d_in[0];
    const float* Wq = (const float*)d_in[1];
    const float* Wk = (const float*)d_in[2];
    const float* Wv = (const float*)d_in[3];
    const float* Wo = (const float*)d_in[4];
    const float* W1 = (const float*)d_in[5];
    const float* W2 = (const float*)d_in[6];
    float* out = (float*)d_out;

    __half *x16, *q16, *k16, *v16, *c16, *h16, *f16;
    __half *wqt, *wkt, *wvt, *wot, *w1t, *w2t;
    float *t0, *h;
    cudaGetSymbolAddress((void**)&x16, g_x16);
    cudaGetSymbolAddress((void**)&q16, g_q16);
    cudaGetSymbolAddress((void**)&k16, g_k16);
    cudaGetSymbolAddress((void**)&v16, g_v16);
    cudaGetSymbolAddress((void**)&c16, g_c16);
    cudaGetSymbolAddress((void**)&h16, g_h16);
    cudaGetSymbolAddress((void**)&f16, g_f16);
    cudaGetSymbolAddress((void**)&t0,  g_t0);
    cudaGetSymbolAddress((void**)&h,   g_h);
    cudaGetSymbolAddress((void**)&wqt, g_wqt);
    cudaGetSymbolAddress((void**)&wkt, g_wkt);
    cudaGetSymbolAddress((void**)&wvt, g_wvt);
    cudaGetSymbolAddress((void**)&wot, g_wot);
    cudaGetSymbolAddress((void**)&w1t, g_w1t);
    cudaGetSymbolAddress((void**)&w2t, g_w2t);

    cudaFuncSetAttribute(attn_h_kernel, cudaFuncAttributeMaxDynamicSharedMemorySize,
                         ATT_DSM);
    cudaFuncSetAttribute((const void*)gemm_h<false, true>,
                         cudaFuncAttributeMaxDynamicSharedMemorySize, GEMM_DSM);
    cudaFuncSetAttribute((const void*)gemm_h<false, false>,
                         cudaFuncAttributeMaxDynamicSharedMemorySize, GEMM_DSM);
    cudaFuncSetAttribute((const void*)gemm_h<true, true>,
                         cudaFuncAttributeMaxDynamicSharedMemorySize, GEMM_DSM);

    // ---- pre-pass: exact tile grid (12288 CTAs, no early-exit waste) ----
    trans_cvt_kernel<<<N_TILES_ALL, 256>>>(
        Wq, Wk, Wv, Wo, W1, W2, wqt, wkt, wvt, wot, w1t, w2t);
    cvt16_kernel<<<(TOKENS * DM / 4 + 255) / 256, 256>>>(
        (const float4*)x, (__half2*)x16, TOKENS * DM / 4);

    dim3 g_qkv(DM / 128, TOKENS / 128, 3);
    dim3 g_dm (DM / 128, TOKENS / 128, 1);
    dim3 g_di (DI / 128, TOKENS / 128, 1);

    gemm_h<false, true><<<g_qkv, 128, GEMM_DSM>>>(
        x16, wqt, wkt, wvt, q16, k16, v16, TOKENS, DM, DM);

    attn_h_kernel<<<dim3(SEQ / 128, NH, BATCH), 256, ATT_DSM>>>(q16, k16, v16, c16);

    gemm_h<false, false><<<g_dm, 128, GEMM_DSM>>>(
        c16, wot, wot, wot, t0, t0, t0, TOKENS, DM, DM);
    add_rmsnorm_kernel<true><<<TOKENS, 256>>>(x, t0, h, h16);

    gemm_h<true, true><<<g_di, 128, GEMM_DSM>>>(
        h16, w1t, w1t, w1t, f16, f16, f16, TOKENS, DI, DM);
    gemm_h<false, false><<<g_dm, 128, GEMM_DSM>>>(
        f16, w2t, w2t, w2t, t0, t0, t0, TOKENS, DM, DI);
    add_rmsnorm_kernel<false><<<TOKENS, 256>>>(h, t0, out, (__half*)nullptr);
}